// round 1
// baseline (speedup 1.0000x reference)
#include <cuda_runtime.h>
#include <cuda_fp16.h>
#include <cstdint>

// Problem constants
#define B_  16
#define I_  2048
#define K_  16      // A_IN
#define O_  64
#define A_  32
#define N_  2048    // O_*A_

// Kernel 1 tiling (votes GEMM + per-CTA sum over i)
#define NI  16              // input capsules per CTA
#define TN  512             // n-tile
#define NT  (N_/TN)         // 4
#define IC  (I_/NI)         // 128

// Kernel 3 tiling (routing pass)
#define TI3 64              // i's per CTA
#define IC3 (I_/TI3)        // 32

// ---- scratch (device globals: no cudaMalloc allowed) ----
__device__ __half g_votes[(size_t)B_ * I_ * N_];        // 128 MB fp16 votes
__device__ float  g_part1[(size_t)IC * B_ * N_];        // 16 MB  (sum-over-i partials, pass1)
__device__ float  g_part2[(size_t)IC3 * B_ * N_];       // 4 MB   (routing pass 2 partials)
__device__ float  g_part3[(size_t)IC3 * B_ * N_];       // 4 MB   (routing pass 3 partials)
__device__ float  g_cum0[B_ * N_];                      // act0
__device__ float  g_cum1[B_ * N_];                      // act0 + act1

// =====================================================================
// Kernel 1: votes[b,i,n] = sum_k x[b,i,k] * W[i,k,n]  (fp32 compute,
// fp16 store) + per-CTA partial of sum_i votes -> g_part1[ic][b][n]
// grid (NT, IC), 256 threads, dyn smem = W tile (32KB) + psum (32KB) + x (1KB)
// =====================================================================
__global__ __launch_bounds__(256) void votes_kernel(const float* __restrict__ x,
                                                    const float* __restrict__ w) {
    extern __shared__ float smem1[];
    float* Wt = smem1;              // [16][TN]
    float* ps = smem1 + 16 * TN;    // [16][TN]
    float* xs = ps + 16 * TN;       // [k][b] = [16][16]

    const int tid = threadIdx.x;
    const int nt  = blockIdx.x;     // n-tile
    const int ic  = blockIdx.y;     // i-chunk
    const int tn  = tid & 127;      // n-thread: owns 4 contiguous n
    const int bg  = tid >> 7;       // 0/1 -> b0 = bg*8
    const int b0  = bg * 8;

    for (int p = tid; p < 16 * TN; p += 256) ps[p] = 0.f;

    for (int ii = 0; ii < NI; ++ii) {
        const int i = ic * NI + ii;

        // stage W[i, :, nt*TN .. +TN]
        const float4* wsrc = reinterpret_cast<const float4*>(w + (size_t)i * K_ * N_ + nt * TN);
        #pragma unroll
        for (int p = tid; p < K_ * (TN / 4); p += 256) {
            int row = p >> 7;           // TN/4 = 128
            int c4  = p & 127;
            reinterpret_cast<float4*>(Wt)[row * (TN / 4) + c4] = wsrc[row * (N_ / 4) + c4];
        }
        // stage x[:, i, :] transposed as xs[k][b]
        {
            int bb = tid >> 4, kk = tid & 15;
            xs[kk * 16 + bb] = x[((size_t)bb * I_ + i) * K_ + kk];
        }
        __syncthreads();

        float acc[8][4];
        #pragma unroll
        for (int j = 0; j < 8; ++j) { acc[j][0] = acc[j][1] = acc[j][2] = acc[j][3] = 0.f; }

        #pragma unroll
        for (int k = 0; k < K_; ++k) {
            float4 wv = reinterpret_cast<const float4*>(Wt)[k * (TN / 4) + tn];
            float4 x0 = reinterpret_cast<const float4*>(xs)[k * 4 + bg * 2 + 0];
            float4 x1 = reinterpret_cast<const float4*>(xs)[k * 4 + bg * 2 + 1];
            float xb[8] = {x0.x, x0.y, x0.z, x0.w, x1.x, x1.y, x1.z, x1.w};
            #pragma unroll
            for (int j = 0; j < 8; ++j) {
                acc[j][0] = fmaf(xb[j], wv.x, acc[j][0]);
                acc[j][1] = fmaf(xb[j], wv.y, acc[j][1]);
                acc[j][2] = fmaf(xb[j], wv.z, acc[j][2]);
                acc[j][3] = fmaf(xb[j], wv.w, acc[j][3]);
            }
        }

        // epilogue: fp16 votes write + psum update
        #pragma unroll
        for (int j = 0; j < 8; ++j) {
            const int b = b0 + j;
            size_t voff = ((size_t)b * I_ + i) * N_ + nt * TN + tn * 4;
            __half2 h0 = __floats2half2_rn(acc[j][0], acc[j][1]);
            __half2 h1 = __floats2half2_rn(acc[j][2], acc[j][3]);
            uint2 pk;
            pk.x = *reinterpret_cast<unsigned*>(&h0);
            pk.y = *reinterpret_cast<unsigned*>(&h1);
            *reinterpret_cast<uint2*>(&g_votes[voff]) = pk;

            float4* pp = reinterpret_cast<float4*>(&ps[b * TN + tn * 4]);
            float4 pv = *pp;
            pv.x += acc[j][0]; pv.y += acc[j][1]; pv.z += acc[j][2]; pv.w += acc[j][3];
            *pp = pv;
        }
        __syncthreads();
    }

    // dump psum -> g_part1[ic][b][n-tile]
    const float4* psv = reinterpret_cast<const float4*>(ps);
    float4* dst = reinterpret_cast<float4*>(g_part1);
    #pragma unroll
    for (int p = tid; p < 16 * (TN / 4); p += 256) {
        int b = p >> 7, c4 = p & 127;
        dst[((size_t)ic * 16 + b) * (N_ / 4) + nt * (TN / 4) + c4] = psv[b * (TN / 4) + c4];
    }
}

// =====================================================================
// Kernel 3: one routing pass. For each (b, i): dist[o] = sum_a votes*cum,
// route = softmax_o(dist), acc[n] += route*votes. Partials per i-chunk.
// grid (IC3, B_), 256 threads (thread t owns n0=t*8..+8, o = t/4)
// =====================================================================
__global__ __launch_bounds__(256) void route_kernel(const float* __restrict__ cum,
                                                    float* __restrict__ part) {
    const int tid = threadIdx.x;
    const int b   = blockIdx.y;
    const int ch  = blockIdx.x;
    const int n0  = tid * 8;
    __shared__ float sd[66];

    float av[8];
    #pragma unroll
    for (int j = 0; j < 8; ++j) av[j] = cum[b * N_ + n0 + j];

    float acc[8] = {0.f, 0.f, 0.f, 0.f, 0.f, 0.f, 0.f, 0.f};
    const __half* vbase = g_votes + ((size_t)b * I_ + (size_t)ch * TI3) * N_ + n0;

    for (int ii = 0; ii < TI3; ++ii) {
        uint4 raw = *reinterpret_cast<const uint4*>(vbase + (size_t)ii * N_);
        float v[8];
        {
            __half2 h; float2 f;
            h = *reinterpret_cast<__half2*>(&raw.x); f = __half22float2(h); v[0] = f.x; v[1] = f.y;
            h = *reinterpret_cast<__half2*>(&raw.y); f = __half22float2(h); v[2] = f.x; v[3] = f.y;
            h = *reinterpret_cast<__half2*>(&raw.z); f = __half22float2(h); v[4] = f.x; v[5] = f.y;
            h = *reinterpret_cast<__half2*>(&raw.w); f = __half22float2(h); v[6] = f.x; v[7] = f.y;
        }
        float dp = 0.f;
        #pragma unroll
        for (int j = 0; j < 8; ++j) dp = fmaf(v[j], av[j], dp);
        dp += __shfl_xor_sync(0xffffffffu, dp, 1);
        dp += __shfl_xor_sync(0xffffffffu, dp, 2);
        if ((tid & 3) == 0) sd[tid >> 2] = dp;
        __syncthreads();
        if (tid < 32) {
            float da = sd[tid], db = sd[tid + 32];
            float mx = fmaxf(da, db);
            #pragma unroll
            for (int s = 16; s > 0; s >>= 1) mx = fmaxf(mx, __shfl_xor_sync(0xffffffffu, mx, s));
            float e = __expf(da - mx) + __expf(db - mx);
            #pragma unroll
            for (int s = 16; s > 0; s >>= 1) e += __shfl_xor_sync(0xffffffffu, e, s);
            if (tid == 0) { sd[64] = mx; sd[65] = 1.f / e; }
        }
        __syncthreads();
        const float route = __expf(dp - sd[64]) * sd[65];
        #pragma unroll
        for (int j = 0; j < 8; ++j) acc[j] = fmaf(route, v[j], acc[j]);
    }

    float4* dst = reinterpret_cast<float4*>(&part[((size_t)ch * B_ + b) * N_ + n0]);
    dst[0] = make_float4(acc[0], acc[1], acc[2], acc[3]);
    dst[1] = make_float4(acc[4], acc[5], acc[6], acc[7]);
}

// =====================================================================
// Squash: reduce partials over chunks, +bias, squash over a (warp = one
// (b,o) capsule). out = squash(pre) (+ prev for cumulative activation).
// grid 128 x 256 threads = 32768 = B*O*A
// =====================================================================
__global__ __launch_bounds__(256) void squash_kernel(const float* __restrict__ part, int nch,
                                                     float scale, const float* __restrict__ bias,
                                                     const float* __restrict__ prev,
                                                     float* __restrict__ out) {
    const int g = blockIdx.x * 256 + threadIdx.x;   // b*N_ + o*A_ + a
    float s = 0.f;
    #pragma unroll 4
    for (int c = 0; c < nch; ++c) s += part[(size_t)c * (B_ * N_) + g];
    const float pre = s * scale + bias[g & (N_ - 1)];
    float ns = pre * pre;
    #pragma unroll
    for (int sft = 16; sft > 0; sft >>= 1) ns += __shfl_xor_sync(0xffffffffu, ns, sft);
    const float sc = sqrtf(ns) / (1.f + ns);
    float act = pre * sc;
    if (prev) act += prev[g];
    out[g] = act;
}

// =====================================================================
extern "C" void kernel_launch(void* const* d_in, const int* in_sizes, int n_in,
                              void* d_out, int out_size) {
    const float* x    = (const float*)d_in[0];
    const float* w    = (const float*)d_in[1];
    const float* bias = (const float*)d_in[2];
    float* out = (float*)d_out;

    const int smem1 = (16 * TN * 2 + 256) * (int)sizeof(float);  // 66560 B
    cudaFuncSetAttribute(votes_kernel, cudaFuncAttributeMaxDynamicSharedMemorySize, smem1);

    void *p1, *p2, *p3, *c0, *c1;
    cudaGetSymbolAddress(&p1, g_part1);
    cudaGetSymbolAddress(&p2, g_part2);
    cudaGetSymbolAddress(&p3, g_part3);
    cudaGetSymbolAddress(&c0, g_cum0);
    cudaGetSymbolAddress(&c1, g_cum1);

    // Pass 1: votes + sum_i partials
    votes_kernel<<<dim3(NT, IC), 256, smem1>>>(x, w);
    // act0 = squash(sum/64 + bias); cum0 = act0
    squash_kernel<<<128, 256>>>((const float*)p1, IC, 1.f / 64.f, bias, nullptr, (float*)c0);
    // Routing iter 1: logits = dist(act0)
    route_kernel<<<dim3(IC3, B_), 256>>>((const float*)c0, (float*)p2);
    // act1 = squash(. + bias); cum1 = act0 + act1
    squash_kernel<<<128, 256>>>((const float*)p2, IC3, 1.f, bias, (const float*)c0, (float*)c1);
    // Routing iter 2: logits = dist(act0) + dist(act1) = dist(cum1)
    route_kernel<<<dim3(IC3, B_), 256>>>((const float*)c1, (float*)p3);
    // Final activation -> d_out
    squash_kernel<<<128, 256>>>((const float*)p3, IC3, 1.f, bias, nullptr, out);
}

// round 2
// speedup vs baseline: 1.5776x; 1.5776x over previous
#include <cuda_runtime.h>
#include <cuda_fp16.h>
#include <cstdint>

// Problem constants
#define B_  16
#define I_  2048
#define K_  16      // A_IN
#define O_  64
#define A_  32
#define N_  2048    // O_*A_

// votes kernel tiling
#define NI  16              // input capsules per CTA
#define TN  512             // n-tile
#define NT  (N_/TN)         // 4
#define IC  (I_/NI)         // 128

// route kernel tiling
#define TI3 32              // i's per CTA
#define IC3 (I_/TI3)        // 64
#define TT  8               // i-tile (phase granularity)

// ---- scratch (device globals: no cudaMalloc allowed) ----
__device__ __half g_votes[(size_t)B_ * I_ * N_];        // 128 MB fp16 votes
__device__ float  g_part1[(size_t)IC * B_ * N_];        // 16 MB
__device__ float  g_part2[(size_t)IC3 * B_ * N_];       // 8 MB
__device__ float  g_part3[(size_t)IC3 * B_ * N_];       // 8 MB
__device__ float  g_cum0[B_ * N_];                      // act0
__device__ float  g_cum1[B_ * N_];                      // act0 + act1

// ---- f32x2 packed-math helpers ----
using u64 = unsigned long long;
__device__ __forceinline__ void fma2(u64& d, u64 a, u64 b) {
    asm("fma.rn.f32x2 %0, %1, %2, %0;" : "+l"(d) : "l"(a), "l"(b));
}
__device__ __forceinline__ void add2(u64& d, u64 a) {
    asm("add.rn.f32x2 %0, %1, %0;" : "+l"(d) : "l"(a));
}
__device__ __forceinline__ float2 unpack2(u64 v) {
    float2 f;
    asm("mov.b64 {%0, %1}, %2;" : "=f"(f.x), "=f"(f.y) : "l"(v));
    return f;
}
__device__ __forceinline__ void cpasync16(uint32_t s, const void* g) {
    asm volatile("cp.async.cg.shared.global [%0], [%1], 16;" :: "r"(s), "l"(g) : "memory");
}
__device__ __forceinline__ void cpcommit() { asm volatile("cp.async.commit_group;" ::: "memory"); }
__device__ __forceinline__ void cpwait0()  { asm volatile("cp.async.wait_group 0;" ::: "memory"); }

// =====================================================================
// votes[b,i,n] = sum_k x[b,i,k]*W[i,k,n], fp32 compute (f32x2), fp16 store.
// Register-resident partial sum over i -> g_part1. cp.async double-buffered W.
// grid (NT, IC), 256 threads. dyn smem = 2*32KB (W) + 2*2KB (x dup pairs).
// Thread: tn = tid&127 owns 4 n, bg = tid>>7 owns 8 b.
// =====================================================================
__global__ __launch_bounds__(256, 2) void votes_kernel(const float* __restrict__ x,
                                                       const float* __restrict__ w) {
    extern __shared__ float smem[];
    float*  Wt0 = smem;                 // [16][TN]
    float*  Wt1 = smem + 16 * TN;       // [16][TN]
    float2* Xs0 = (float2*)(smem + 32 * TN);        // [16][16] (x,x) pairs
    float2* Xs1 = Xs0 + 256;

    const int tid = threadIdx.x;
    const int nt  = blockIdx.x;
    const int ic  = blockIdx.y;
    const int tn  = tid & 127;
    const int bg  = tid >> 7;
    const int b0  = bg * 8;
    const int i0  = ic * NI;
    const int bb  = tid >> 4, kk = tid & 15;        // x-staging role

    u64 accsum[8][2];
    #pragma unroll
    for (int j = 0; j < 8; ++j) { accsum[j][0] = 0ull; accsum[j][1] = 0ull; }

    // ---- prologue: stage i0 into buffer 0 ----
    {
        const float4* wsrc = (const float4*)(w + (size_t)i0 * K_ * N_ + nt * TN);
        uint32_t wdst = (uint32_t)__cvta_generic_to_shared(Wt0);
        #pragma unroll
        for (int p = tid; p < K_ * (TN / 4); p += 256)
            cpasync16(wdst + p * 16, &wsrc[(p >> 7) * (N_ / 4) + (p & 127)]);
        float xv = x[((size_t)bb * I_ + i0) * K_ + kk];
        Xs0[kk * 16 + bb] = make_float2(xv, xv);
        cpcommit();
        cpwait0();
    }
    __syncthreads();

    for (int ii = 0; ii < NI; ++ii) {
        const int i = i0 + ii;
        const float*  Wc = (ii & 1) ? Wt1 : Wt0;
        const float2* Xc = (ii & 1) ? Xs1 : Xs0;
        float*  Wn = (ii & 1) ? Wt0 : Wt1;
        float2* Xn = (ii & 1) ? Xs0 : Xs1;

        float xv = 0.f;
        if (ii + 1 < NI) {
            const float4* wsrc = (const float4*)(w + (size_t)(i + 1) * K_ * N_ + nt * TN);
            uint32_t wdst = (uint32_t)__cvta_generic_to_shared(Wn);
            #pragma unroll
            for (int p = tid; p < K_ * (TN / 4); p += 256)
                cpasync16(wdst + p * 16, &wsrc[(p >> 7) * (N_ / 4) + (p & 127)]);
            cpcommit();
            xv = x[((size_t)bb * I_ + (i + 1)) * K_ + kk];
        }

        u64 acc[8][2];
        #pragma unroll
        for (int j = 0; j < 8; ++j) { acc[j][0] = 0ull; acc[j][1] = 0ull; }

        #pragma unroll 4
        for (int k = 0; k < K_; ++k) {
            ulonglong2 wv = *(const ulonglong2*)&Wc[k * TN + tn * 4];
            #pragma unroll
            for (int j = 0; j < 8; ++j) {
                u64 xb = *(const u64*)&Xc[k * 16 + b0 + j];   // broadcast LDS.64
                fma2(acc[j][0], xb, wv.x);
                fma2(acc[j][1], xb, wv.y);
            }
        }

        // epilogue: fp16 store + register partial-sum
        #pragma unroll
        for (int j = 0; j < 8; ++j) {
            float2 f01 = unpack2(acc[j][0]);
            float2 f23 = unpack2(acc[j][1]);
            __half2 h0 = __floats2half2_rn(f01.x, f01.y);
            __half2 h1 = __floats2half2_rn(f23.x, f23.y);
            uint2 pk;
            pk.x = *reinterpret_cast<unsigned*>(&h0);
            pk.y = *reinterpret_cast<unsigned*>(&h1);
            size_t voff = ((size_t)(b0 + j) * I_ + i) * N_ + nt * TN + tn * 4;
            *reinterpret_cast<uint2*>(&g_votes[voff]) = pk;
            add2(accsum[j][0], acc[j][0]);
            add2(accsum[j][1], acc[j][1]);
        }

        if (ii + 1 < NI) {
            Xn[kk * 16 + bb] = make_float2(xv, xv);
            cpwait0();
        }
        __syncthreads();
    }

    // dump register partials
    #pragma unroll
    for (int j = 0; j < 8; ++j) {
        ulonglong2 v; v.x = accsum[j][0]; v.y = accsum[j][1];
        *(ulonglong2*)&g_part1[((size_t)ic * B_ + (b0 + j)) * N_ + nt * TN + tn * 4] = v;
    }
}

// =====================================================================
// route pass, phase-split. grid (IC3, B_), 256 threads.
// Thread owns 8 n (n0 = tid*8), o = tid/4. Tiles of TT=8 i's:
//   ph1: 8 independent LDG.128 -> registers, dot with cum -> logits smem
//   ph2: warp-per-row softmax
//   ph3: acc += route * votes (votes from registers)
// =====================================================================
__global__ __launch_bounds__(256) void route_kernel(const float* __restrict__ cum,
                                                    float* __restrict__ part) {
    const int tid  = threadIdx.x;
    const int b    = blockIdx.y;
    const int ch   = blockIdx.x;
    const int n0   = tid * 8;
    const int o    = tid >> 2;
    const int lane = tid & 31;
    const int wrp  = tid >> 5;

    __shared__ float sl[TT][O_];
    __shared__ float sr[TT][O_];

    float av[8];
    {
        const float4* cp4 = (const float4*)(cum + b * N_ + n0);
        float4 a0 = cp4[0], a1 = cp4[1];
        av[0] = a0.x; av[1] = a0.y; av[2] = a0.z; av[3] = a0.w;
        av[4] = a1.x; av[5] = a1.y; av[6] = a1.z; av[7] = a1.w;
    }

    float acc[8] = {0.f, 0.f, 0.f, 0.f, 0.f, 0.f, 0.f, 0.f};
    const __half* vb = g_votes + ((size_t)b * I_ + (size_t)ch * TI3) * N_ + n0;

    for (int t = 0; t < TI3 / TT; ++t) {
        uint4 vr[TT];
        #pragma unroll
        for (int ii = 0; ii < TT; ++ii)
            vr[ii] = *(const uint4*)(vb + ((size_t)(t * TT + ii)) * N_);

        #pragma unroll
        for (int ii = 0; ii < TT; ++ii) {
            float2 f0 = __half22float2(*(__half2*)&vr[ii].x);
            float2 f1 = __half22float2(*(__half2*)&vr[ii].y);
            float2 f2 = __half22float2(*(__half2*)&vr[ii].z);
            float2 f3 = __half22float2(*(__half2*)&vr[ii].w);
            float dp = f0.x * av[0];
            dp = fmaf(f0.y, av[1], dp); dp = fmaf(f1.x, av[2], dp);
            dp = fmaf(f1.y, av[3], dp); dp = fmaf(f2.x, av[4], dp);
            dp = fmaf(f2.y, av[5], dp); dp = fmaf(f3.x, av[6], dp);
            dp = fmaf(f3.y, av[7], dp);
            dp += __shfl_xor_sync(0xffffffffu, dp, 1);
            dp += __shfl_xor_sync(0xffffffffu, dp, 2);
            if ((tid & 3) == 0) sl[ii][o] = dp;
        }
        __syncthreads();

        // softmax over 64 o for row `wrp`
        {
            float d0 = sl[wrp][lane], d1 = sl[wrp][lane + 32];
            float mx = fmaxf(d0, d1);
            #pragma unroll
            for (int s = 16; s > 0; s >>= 1) mx = fmaxf(mx, __shfl_xor_sync(0xffffffffu, mx, s));
            float e0 = __expf(d0 - mx), e1 = __expf(d1 - mx);
            float e = e0 + e1;
            #pragma unroll
            for (int s = 16; s > 0; s >>= 1) e += __shfl_xor_sync(0xffffffffu, e, s);
            float inv = 1.f / e;
            sr[wrp][lane]      = e0 * inv;
            sr[wrp][lane + 32] = e1 * inv;
        }
        __syncthreads();

        #pragma unroll
        for (int ii = 0; ii < TT; ++ii) {
            float r = sr[ii][o];
            float2 f0 = __half22float2(*(__half2*)&vr[ii].x);
            float2 f1 = __half22float2(*(__half2*)&vr[ii].y);
            float2 f2 = __half22float2(*(__half2*)&vr[ii].z);
            float2 f3 = __half22float2(*(__half2*)&vr[ii].w);
            acc[0] = fmaf(r, f0.x, acc[0]); acc[1] = fmaf(r, f0.y, acc[1]);
            acc[2] = fmaf(r, f1.x, acc[2]); acc[3] = fmaf(r, f1.y, acc[3]);
            acc[4] = fmaf(r, f2.x, acc[4]); acc[5] = fmaf(r, f2.y, acc[5]);
            acc[6] = fmaf(r, f3.x, acc[6]); acc[7] = fmaf(r, f3.y, acc[7]);
        }
        __syncthreads();
    }

    float4* dst = (float4*)&part[((size_t)ch * B_ + b) * N_ + n0];
    dst[0] = make_float4(acc[0], acc[1], acc[2], acc[3]);
    dst[1] = make_float4(acc[4], acc[5], acc[6], acc[7]);
}

// =====================================================================
// squash: reduce nch chunk partials (float4 lanes, chunk-sliced), +bias,
// squash over a. grid 128 CTAs x 256 threads.
// =====================================================================
__global__ __launch_bounds__(256) void squash_kernel(const float* __restrict__ part, int nch,
                                                     float scale, const float* __restrict__ bias,
                                                     const float* __restrict__ prev,
                                                     float* __restrict__ out) {
    __shared__ float4 sred[256];
    const int tid = threadIdx.x;
    const int f = tid & 63, slice = tid >> 6;
    const int gf4 = blockIdx.x * 64 + f;          // float4 index into [B_*N_/4)

    float4 s = make_float4(0.f, 0.f, 0.f, 0.f);
    for (int c = slice; c < nch; c += 4) {
        float4 v = ((const float4*)part)[(size_t)c * (B_ * N_ / 4) + gf4];
        s.x += v.x; s.y += v.y; s.z += v.z; s.w += v.w;
    }
    sred[tid] = s;
    __syncthreads();

    if (tid < 64) {
        float4 t0 = sred[f], t1 = sred[64 + f], t2 = sred[128 + f], t3 = sred[192 + f];
        float4 tt;
        tt.x = t0.x + t1.x + t2.x + t3.x;
        tt.y = t0.y + t1.y + t2.y + t3.y;
        tt.z = t0.z + t1.z + t2.z + t3.z;
        tt.w = t0.w + t1.w + t2.w + t3.w;
        const int n4 = gf4 & (N_ / 4 - 1);
        float4 bv = ((const float4*)bias)[n4];
        float4 pre;
        pre.x = tt.x * scale + bv.x;
        pre.y = tt.y * scale + bv.y;
        pre.z = tt.z * scale + bv.z;
        pre.w = tt.w * scale + bv.w;
        float ns = pre.x * pre.x + pre.y * pre.y + pre.z * pre.z + pre.w * pre.w;
        ns += __shfl_xor_sync(0xffffffffu, ns, 1);
        ns += __shfl_xor_sync(0xffffffffu, ns, 2);
        ns += __shfl_xor_sync(0xffffffffu, ns, 4);
        const float sc = sqrtf(ns) / (1.f + ns);
        float4 act;
        act.x = pre.x * sc; act.y = pre.y * sc; act.z = pre.z * sc; act.w = pre.w * sc;
        if (prev) {
            float4 pv = ((const float4*)prev)[gf4];
            act.x += pv.x; act.y += pv.y; act.z += pv.z; act.w += pv.w;
        }
        ((float4*)out)[gf4] = act;
    }
}

// =====================================================================
extern "C" void kernel_launch(void* const* d_in, const int* in_sizes, int n_in,
                              void* d_out, int out_size) {
    const float* x    = (const float*)d_in[0];
    const float* w    = (const float*)d_in[1];
    const float* bias = (const float*)d_in[2];
    float* out = (float*)d_out;

    const int smem1 = 2 * 16 * TN * (int)sizeof(float) + 2 * 256 * (int)sizeof(float2); // 69632
    cudaFuncSetAttribute(votes_kernel, cudaFuncAttributeMaxDynamicSharedMemorySize, smem1);

    void *p1, *p2, *p3, *c0, *c1;
    cudaGetSymbolAddress(&p1, g_part1);
    cudaGetSymbolAddress(&p2, g_part2);
    cudaGetSymbolAddress(&p3, g_part3);
    cudaGetSymbolAddress(&c0, g_cum0);
    cudaGetSymbolAddress(&c1, g_cum1);

    votes_kernel<<<dim3(NT, IC), 256, smem1>>>(x, w);
    squash_kernel<<<128, 256>>>((const float*)p1, IC, 1.f / 64.f, bias, nullptr, (float*)c0);
    route_kernel<<<dim3(IC3, B_), 256>>>((const float*)c0, (float*)p2);
    squash_kernel<<<128, 256>>>((const float*)p2, IC3, 1.f, bias, (const float*)c0, (float*)c1);
    route_kernel<<<dim3(IC3, B_), 256>>>((const float*)c1, (float*)p3);
    squash_kernel<<<128, 256>>>((const float*)p3, IC3, 1.f, bias, nullptr, out);
}